// round 14
// baseline (speedup 1.0000x reference)
#include <cuda_runtime.h>
#include <cuda_bf16.h>
#include <cstdint>

#define BB    16
#define NTOK  1024
#define CC    512
#define M_TOT (BB * NTOK)     // 16384
#define NH    8
#define QKV_N 1536
#define ATT_N 512
#define KW    (CC / 2)        // 256 u32 words per K=512 row (bf16-pair)
#define SCALE_L2E 0.18033688011112042f

__device__ uint32_t g_qkv [(size_t)M_TOT * (QKV_N / 2)];
__device__ uint32_t g_att [(size_t)M_TOT * (ATT_N / 2)];
__device__ uint32_t g_wqkvT[(size_t)QKV_N * KW];
__device__ uint32_t g_woutT[(size_t)ATT_N * KW];

__device__ __forceinline__ uint32_t packbf(float lo, float hi) {
    __nv_bfloat162 v = __floats2bfloat162_rn(lo, hi);
    return *(uint32_t*)&v;
}
__device__ __forceinline__ float ex2(float x) {
    float r; asm("ex2.approx.f32 %0, %1;" : "=f"(r) : "f"(x)); return r;
}
__device__ __forceinline__ uint32_t smem_u32(const void* p) {
    return (uint32_t)__cvta_generic_to_shared(p);
}

__device__ __forceinline__ void mma_bf16(float* d, const uint32_t* a, const uint32_t* b) {
    asm volatile(
        "mma.sync.aligned.m16n8k16.row.col.f32.bf16.bf16.f32 "
        "{%0,%1,%2,%3}, {%4,%5,%6,%7}, {%8,%9}, {%0,%1,%2,%3};"
        : "+f"(d[0]), "+f"(d[1]), "+f"(d[2]), "+f"(d[3])
        : "r"(a[0]), "r"(a[1]), "r"(a[2]), "r"(a[3]), "r"(b[0]), "r"(b[1]));
}
__device__ __forceinline__ void ldmx4(
    uint32_t& r0, uint32_t& r1, uint32_t& r2, uint32_t& r3, const void* p) {
    uint32_t a = smem_u32(p);
    asm volatile("ldmatrix.sync.aligned.m8n8.x4.shared.b16 {%0,%1,%2,%3}, [%4];"
                 : "=r"(r0), "=r"(r1), "=r"(r2), "=r"(r3) : "r"(a));
}
__device__ __forceinline__ void ldmx4t(
    uint32_t& r0, uint32_t& r1, uint32_t& r2, uint32_t& r3, const void* p) {
    uint32_t a = smem_u32(p);
    asm volatile("ldmatrix.sync.aligned.m8n8.x4.trans.shared.b16 {%0,%1,%2,%3}, [%4];"
                 : "=r"(r0), "=r"(r1), "=r"(r2), "=r"(r3) : "r"(a));
}

// ---------------------------------------------------------------------------
// prep: w[K][N] fp32 -> wt[N][K/2] bf16-pair (W^T, K-major)
// ---------------------------------------------------------------------------
__global__ void pack_wt(const float* __restrict__ w, uint32_t* __restrict__ wt, int N) {
    int n  = blockIdx.x * 256 + threadIdx.x;
    int kp = blockIdx.y;
    float a = w[(size_t)(2 * kp) * N + n];
    float b = w[(size_t)(2 * kp + 1) * N + n];
    wt[(size_t)n * KW + kp] = packbf(a, b);
}

// ---------------------------------------------------------------------------
// bf16 GEMM: C[M,N] = A[M,512] @ Bt[N,512]^T + bias (+resid).
// BM=BN=128, 256 thr / 8 warps (4x2), warp tile 32x64.
// AF32=false: A is bf16-pair gmem, BK=64 (R11/R13 measured-best config).
// AF32=true : A is fp32 gmem, converted in-register; BK=32 (reg budget).
// ---------------------------------------------------------------------------
template <bool RES, bool OBF16, bool QSC, bool AF32>
__global__ __launch_bounds__(256, 2) void tgemm(
    const void* __restrict__ Ap, const uint32_t* __restrict__ Bt,
    const float* __restrict__ bias, const float* __restrict__ resid,
    void* __restrict__ Cp, int M, int N)
{
    constexpr int BKW = AF32 ? 16 : 32;      // u32 words per row per chunk
    constexpr int RS  = BKW + 4;             // row stride (padded)
    constexpr int TILES = AF32 ? 16 : 8;     // K = 512
    constexpr int KKN = BKW / 8;             // k16-chunks per tile

    extern __shared__ __align__(16) uint32_t sm[];
    uint32_t* Abuf[2] = {sm, sm + 128 * RS};
    uint32_t* Bbuf[2] = {sm + 2 * 128 * RS, sm + 3 * 128 * RS};

    const int tid  = threadIdx.x;
    const int warp = tid >> 5, lane = tid & 31;
    const int gid  = lane >> 2, tig = lane & 3;
    const int wr   = warp >> 1, wc = warp & 1;
    const int bx = blockIdx.x, by = blockIdx.y;

    const float*    Af = (const float*)Ap    + (size_t)(by * 128) * CC;
    const uint32_t* Ab = (const uint32_t*)Ap + (size_t)(by * 128) * KW;
    const uint32_t* Bg = Bt + (size_t)(bx * 128) * KW;

    float acc[2][8][4];
#pragma unroll
    for (int mt = 0; mt < 2; mt++)
#pragma unroll
        for (int nt = 0; nt < 8; nt++)
#pragma unroll
            for (int r = 0; r < 4; r++) acc[mt][nt][r] = 0.f;

    // loaders
    float4 fa[4];        // AF32: 4 float4 (128 rows x 8 float4-segs)
    uint4  ra[4];        // bf16: 4 uint4  (128 rows x 8 uint4-segs)
    uint4  rb[4];        // B: BK64 -> 4 uint4; BK32 -> 2 uint4 (upper unused)

    auto ldg = [&](int c) {
        if (AF32) {
#pragma unroll
            for (int i = 0; i < 4; i++) {
                int j = tid + i * 256;        // 1024 tasks: r = j>>3, seg = j&7
                int r = j >> 3, seg = j & 7;
                fa[i] = *(const float4*)(Af + (size_t)r * CC + c * 32 + seg * 4);
            }
#pragma unroll
            for (int i = 0; i < 2; i++) {
                int j = tid + i * 256;        // 512 tasks: r = j>>2, seg = j&3
                int r = j >> 2, seg = j & 3;
                rb[i] = *(const uint4*)(Bg + (size_t)r * KW + c * 16 + seg * 4);
            }
        } else {
#pragma unroll
            for (int i = 0; i < 4; i++) {
                int j = tid + i * 256;
                int r = j >> 3, seg = j & 7;
                ra[i] = *(const uint4*)(Ab + (size_t)r * KW + c * 32 + seg * 4);
                rb[i] = *(const uint4*)(Bg + (size_t)r * KW + c * 32 + seg * 4);
            }
        }
    };
    auto sts = [&](int s) {
        if (AF32) {
#pragma unroll
            for (int i = 0; i < 4; i++) {
                int j = tid + i * 256;
                int r = j >> 3, seg = j & 7;
                uint2 v;
                v.x = packbf(fa[i].x, fa[i].y);
                v.y = packbf(fa[i].z, fa[i].w);
                *(uint2*)&Abuf[s][r * RS + seg * 2] = v;
            }
#pragma unroll
            for (int i = 0; i < 2; i++) {
                int j = tid + i * 256;
                int r = j >> 2, seg = j & 3;
                *(uint4*)&Bbuf[s][r * RS + seg * 4] = rb[i];
            }
        } else {
#pragma unroll
            for (int i = 0; i < 4; i++) {
                int j = tid + i * 256;
                int r = j >> 3, seg = j & 7;
                *(uint4*)&Abuf[s][r * RS + seg * 4] = ra[i];
                *(uint4*)&Bbuf[s][r * RS + seg * 4] = rb[i];
            }
        }
    };

    ldg(0); sts(0);
    __syncthreads();

    for (int t = 0; t < TILES; t++) {
        const int s = t & 1;
        if (t + 1 < TILES) ldg(t + 1);

        const uint32_t* As = Abuf[s];
        const uint32_t* Bs = Bbuf[s];

#pragma unroll
        for (int kkk = 0; kkk < KKN; kkk++) {
            uint32_t af[2][4];
#pragma unroll
            for (int mt = 0; mt < 2; mt++) {
                int mb = wr * 32 + mt * 16;
                ldmx4(af[mt][0], af[mt][1], af[mt][2], af[mt][3],
                      &As[(mb + (lane & 15)) * RS + kkk * 8 + (lane >> 4) * 4]);
            }
#pragma unroll
            for (int nt2 = 0; nt2 < 4; nt2++) {
                uint32_t r0, r1, r2, r3;
                int rr = wc * 64 + nt2 * 16 + (lane & 7) + ((lane >> 4) << 3);
                int ww = kkk * 8 + ((lane & 8) >> 1);
                ldmx4(r0, r1, r2, r3, &Bs[rr * RS + ww]);
                uint32_t b0[2] = {r0, r1};
                uint32_t b1[2] = {r2, r3};
#pragma unroll
                for (int mt = 0; mt < 2; mt++) {
                    mma_bf16(acc[mt][2 * nt2 + 0], af[mt], b0);
                    mma_bf16(acc[mt][2 * nt2 + 1], af[mt], b1);
                }
            }
        }

        if (t + 1 < TILES) sts(s ^ 1);
        __syncthreads();
    }

    // ---- epilogue ----
#pragma unroll
    for (int mt = 0; mt < 2; mt++) {
#pragma unroll
        for (int r2 = 0; r2 < 2; r2++) {
            int row = by * 128 + wr * 32 + mt * 16 + gid + r2 * 8;
#pragma unroll
            for (int nt = 0; nt < 8; nt++) {
                int col = bx * 128 + wc * 64 + nt * 8 + tig * 2;
                float2 bz = *(const float2*)(bias + col);
                float ox = acc[mt][nt][r2 * 2 + 0] + bz.x;
                float oy = acc[mt][nt][r2 * 2 + 1] + bz.y;
                if (RES) {
                    float2 rr = *(const float2*)(resid + (size_t)row * N + col);
                    ox += rr.x; oy += rr.y;
                }
                if (QSC && ((col % 192) < 64)) { ox *= SCALE_L2E; oy *= SCALE_L2E; }
                if (OBF16) {
                    ((uint32_t*)Cp)[(size_t)row * (N / 2) + col / 2] = packbf(ox, oy);
                } else {
                    float2 o; o.x = ox; o.y = oy;
                    *(float2*)((float*)Cp + (size_t)row * N + col) = o;
                }
            }
        }
    }
}

#define TG_SMEM_BF16 (4 * 128 * 36 * 4)   // 72 KB (BK=64)
#define TG_SMEM_F32  (4 * 128 * 20 * 4)   // 40 KB (BK=32)

// ---------------------------------------------------------------------------
// Flash attention: CTA = 128 queries x (b,h), 8 warps x 16 rows,
// fixed-max ex2 softmax, P in registers, double-buffered K/V,
// SINGLE sync per tile (buffer s^1 free since end of tile kt-1).
// ---------------------------------------------------------------------------
__global__ __launch_bounds__(256, 2) void fattn(
    const uint32_t* __restrict__ qkv, uint32_t* __restrict__ out)
{
    __shared__ uint32_t KV[2][2][64 * 36];   // 36 KB

    const int tid  = threadIdx.x;
    const int warp = tid >> 5, lane = tid & 31;
    const int gid  = lane >> 2, tig = lane & 3;
    const int wrow = warp * 16;
    const int qt = blockIdx.x, h = blockIdx.y, b = blockIdx.z;

    const uint32_t* base = qkv + ((size_t)b * NTOK) * (QKV_N / 2) + h * 96;

    // ---- stage Q into KV region, extract frags ----
    {
        uint32_t* qs = &KV[0][0][0];
#pragma unroll
        for (int i = 0; i < 4; i++) {
            int j = tid + i * 256;
            int r = j >> 3, seg = j & 7;
            *(uint4*)&qs[r * 36 + seg * 4] =
                *(const uint4*)(base + (size_t)(qt * 128 + r) * (QKV_N / 2) + seg * 4);
        }
    }
    __syncthreads();

    uint32_t qf[4][4];
    {
        const uint32_t* qs = &KV[0][0][0];
#pragma unroll
        for (int kki = 0; kki < 4; kki++)
            ldmx4(qf[kki][0], qf[kki][1], qf[kki][2], qf[kki][3],
                  &qs[(wrow + (lane & 15)) * 36 + kki * 8 + (lane >> 4) * 4]);
    }
    __syncthreads();

    uint4 pre[4];
    auto ldg_kv = [&](int kt) {
        const uint32_t* kb = base + (size_t)(kt * 64) * (QKV_N / 2);
#pragma unroll
        for (int i = 0; i < 4; i++) {
            int j = tid + i * 256;
            int kv = j >> 9, jj = j & 511;
            int r = jj >> 3, seg = jj & 7;
            pre[i] = *(const uint4*)(kb + (size_t)r * (QKV_N / 2) + 32 + kv * 32
                                        + seg * 4);
        }
    };
    auto sts_kv = [&](int s) {
#pragma unroll
        for (int i = 0; i < 4; i++) {
            int j = tid + i * 256;
            int kv = j >> 9, jj = j & 511;
            int r = jj >> 3, seg = jj & 7;
            *(uint4*)&KV[s][kv][r * 36 + seg * 4] = pre[i];
        }
    };

    float o[8][4];
#pragma unroll
    for (int nt = 0; nt < 8; nt++)
#pragma unroll
        for (int r = 0; r < 4; r++) o[nt][r] = 0.f;
    float l0 = 0.f, l1 = 0.f;

    ldg_kv(0);
    sts_kv(0);
    __syncthreads();

    for (int kt = 0; kt < 16; kt++) {
        const int s = kt & 1;
        if (kt + 1 < 16) ldg_kv(kt + 1);

        const uint32_t* ks = &KV[s][0][0];
        const uint32_t* vs = &KV[s][1][0];

        // ---- S = Q @ K^T ----
        float sc[8][4];
#pragma unroll
        for (int nt = 0; nt < 8; nt++)
#pragma unroll
            for (int r = 0; r < 4; r++) sc[nt][r] = 0.f;
#pragma unroll
        for (int kki = 0; kki < 4; kki++) {
#pragma unroll
            for (int nt2 = 0; nt2 < 4; nt2++) {
                uint32_t r0, r1, r2, r3;
                int rr = nt2 * 16 + (lane & 7) + ((lane >> 4) << 3);
                int ww = kki * 8 + ((lane & 8) >> 1);
                ldmx4(r0, r1, r2, r3, &ks[rr * 36 + ww]);
                uint32_t b0[2] = {r0, r1};
                uint32_t b1[2] = {r2, r3};
                mma_bf16(sc[2 * nt2 + 0], qf[kki], b0);
                mma_bf16(sc[2 * nt2 + 1], qf[kki], b1);
            }
        }

        // ---- fixed-max softmax: p = ex2(s) ----
        uint32_t pa[4][4];
#pragma unroll
        for (int nt = 0; nt < 8; nt++) {
            float p0 = ex2(sc[nt][0]);
            float p1 = ex2(sc[nt][1]);
            float p2 = ex2(sc[nt][2]);
            float p3 = ex2(sc[nt][3]);
            l0 += p0 + p1;
            l1 += p2 + p3;
            sc[nt][0] = p0; sc[nt][1] = p1; sc[nt][2] = p2; sc[nt][3] = p3;
        }
#pragma unroll
        for (int kkk = 0; kkk < 4; kkk++) {
            pa[kkk][0] = packbf(sc[2 * kkk    ][0], sc[2 * kkk    ][1]);
            pa[kkk][1] = packbf(sc[2 * kkk    ][2], sc[2 * kkk    ][3]);
            pa[kkk][2] = packbf(sc[2 * kkk + 1][0], sc[2 * kkk + 1][1]);
            pa[kkk][3] = packbf(sc[2 * kkk + 1][2], sc[2 * kkk + 1][3]);
        }

        // ---- O += P @ V ----
#pragma unroll
        for (int kkk = 0; kkk < 4; kkk++) {
#pragma unroll
            for (int ntp = 0; ntp < 4; ntp++) {
                uint32_t r0, r1, r2, r3;
                ldmx4t(r0, r1, r2, r3,
                       &vs[(kkk * 16 + (lane & 15)) * 36 + ntp * 8 + (lane >> 4) * 4]);
                uint32_t vb0[2] = {r0, r1};
                uint32_t vb1[2] = {r2, r3};
                mma_bf16(o[2 * ntp + 0], pa[kkk], vb0);
                mma_bf16(o[2 * ntp + 1], pa[kkk], vb1);
            }
        }

        // single barrier per tile: buffer s^1 was drained by end-of-(kt-1) sync
        if (kt + 1 < 16) sts_kv(s ^ 1);
        __syncthreads();
    }

    // ---- epilogue ----
    l0 += __shfl_xor_sync(0xffffffffu, l0, 1);
    l0 += __shfl_xor_sync(0xffffffffu, l0, 2);
    l1 += __shfl_xor_sync(0xffffffffu, l1, 1);
    l1 += __shfl_xor_sync(0xffffffffu, l1, 2);
    float i0 = 1.f / l0, i1 = 1.f / l1;

    int row = b * NTOK + qt * 128 + wrow + gid;
    uint32_t* op0 = out + (size_t)row * (ATT_N / 2) + h * 32;
    uint32_t* op1 = out + (size_t)(row + 8) * (ATT_N / 2) + h * 32;
#pragma unroll
    for (int nt = 0; nt < 8; nt++) {
        op0[nt * 4 + tig] = packbf(o[nt][0] * i0, o[nt][1] * i0);
        op1[nt * 4 + tig] = packbf(o[nt][2] * i1, o[nt][3] * i1);
    }
}

// ---------------------------------------------------------------------------
extern "C" void kernel_launch(void* const* d_in, const int* in_sizes, int n_in,
                              void* d_out, int out_size)
{
    const float* ft    = (const float*)d_in[0];
    const float* w_qkv = (const float*)d_in[1];
    const float* b_qkv = (const float*)d_in[2];
    const float* w_out = (const float*)d_in[3];
    const float* b_out = (const float*)d_in[4];
    float* out = (float*)d_out;

    uint32_t *qkv, *att, *wqkvT, *woutT;
    cudaGetSymbolAddress((void**)&qkv,   g_qkv);
    cudaGetSymbolAddress((void**)&att,   g_att);
    cudaGetSymbolAddress((void**)&wqkvT, g_wqkvT);
    cudaGetSymbolAddress((void**)&woutT, g_woutT);

    cudaFuncSetAttribute(tgemm<false, true, true, true>,
                         cudaFuncAttributeMaxDynamicSharedMemorySize, TG_SMEM_F32);
    cudaFuncSetAttribute(tgemm<true, false, false, false>,
                         cudaFuncAttributeMaxDynamicSharedMemorySize, TG_SMEM_BF16);

    { dim3 g(QKV_N / 256, KW); pack_wt<<<g, 256>>>(w_qkv, wqkvT, QKV_N); }
    { dim3 g(ATT_N / 256, KW); pack_wt<<<g, 256>>>(w_out, woutT, ATT_N); }

    // 1) QKV projection: fp32 A read directly (no cvt_x), bf16 out,
    //    Q cols pre-scaled by SCALE*log2e
    {
        dim3 grid(QKV_N / 128, M_TOT / 128);
        tgemm<false, true, true, true><<<grid, 256, TG_SMEM_F32>>>(
            ft, wqkvT, b_qkv, nullptr, qkv, M_TOT, QKV_N);
    }
    // 2) attention
    {
        dim3 grid(NTOK / 128, NH, BB);
        fattn<<<grid, 256>>>(qkv, att);
    }
    // 3) output projection: bf16 A, fp32 out + bias + residual
    {
        dim3 grid(ATT_N / 128, M_TOT / 128);
        tgemm<true, false, false, false><<<grid, 256, TG_SMEM_BF16>>>(
            att, woutT, b_out, ft, out, M_TOT, ATT_N);
    }
}

// round 15
// speedup vs baseline: 1.1014x; 1.1014x over previous
#include <cuda_runtime.h>
#include <cuda_bf16.h>
#include <cstdint>

#define BB    16
#define NTOK  1024
#define CC    512
#define M_TOT (BB * NTOK)     // 16384
#define NH    8
#define QKV_N 1536
#define ATT_N 512
#define KW    (CC / 2)        // 256 u32 words per K=512 row (bf16-pair)
#define SCALE_L2E 0.18033688011112042f

__device__ uint32_t g_xbf [(size_t)M_TOT * KW];
__device__ uint32_t g_qkv [(size_t)M_TOT * (QKV_N / 2)];
__device__ uint32_t g_att [(size_t)M_TOT * (ATT_N / 2)];
__device__ uint32_t g_wqkvT[(size_t)QKV_N * KW];
__device__ uint32_t g_woutT[(size_t)ATT_N * KW];

__device__ __forceinline__ uint32_t packbf(float lo, float hi) {
    __nv_bfloat162 v = __floats2bfloat162_rn(lo, hi);
    return *(uint32_t*)&v;
}
__device__ __forceinline__ float ex2(float x) {
    float r; asm("ex2.approx.f32 %0, %1;" : "=f"(r) : "f"(x)); return r;
}
__device__ __forceinline__ uint32_t smem_u32(const void* p) {
    return (uint32_t)__cvta_generic_to_shared(p);
}

__device__ __forceinline__ void mma_bf16(float* d, const uint32_t* a, const uint32_t* b) {
    asm volatile(
        "mma.sync.aligned.m16n8k16.row.col.f32.bf16.bf16.f32 "
        "{%0,%1,%2,%3}, {%4,%5,%6,%7}, {%8,%9}, {%0,%1,%2,%3};"
        : "+f"(d[0]), "+f"(d[1]), "+f"(d[2]), "+f"(d[3])
        : "r"(a[0]), "r"(a[1]), "r"(a[2]), "r"(a[3]), "r"(b[0]), "r"(b[1]));
}
__device__ __forceinline__ void ldmx4(
    uint32_t& r0, uint32_t& r1, uint32_t& r2, uint32_t& r3, const void* p) {
    uint32_t a = smem_u32(p);
    asm volatile("ldmatrix.sync.aligned.m8n8.x4.shared.b16 {%0,%1,%2,%3}, [%4];"
                 : "=r"(r0), "=r"(r1), "=r"(r2), "=r"(r3) : "r"(a));
}
__device__ __forceinline__ void ldmx4t(
    uint32_t& r0, uint32_t& r1, uint32_t& r2, uint32_t& r3, const void* p) {
    uint32_t a = smem_u32(p);
    asm volatile("ldmatrix.sync.aligned.m8n8.x4.trans.shared.b16 {%0,%1,%2,%3}, [%4];"
                 : "=r"(r0), "=r"(r1), "=r"(r2), "=r"(r3) : "r"(a));
}

// ---------------------------------------------------------------------------
// prep kernels
// ---------------------------------------------------------------------------
__global__ void cvt_x(const float* __restrict__ x, uint32_t* __restrict__ xb, int n) {
    int i = blockIdx.x * 256 + threadIdx.x;
    if (i >= n) return;
    float2 v = ((const float2*)x)[i];
    xb[i] = packbf(v.x, v.y);
}
__global__ void pack_wt(const float* __restrict__ w, uint32_t* __restrict__ wt, int N) {
    int n  = blockIdx.x * 256 + threadIdx.x;
    int kp = blockIdx.y;
    float a = w[(size_t)(2 * kp) * N + n];
    float b = w[(size_t)(2 * kp + 1) * N + n];
    wt[(size_t)n * KW + kp] = packbf(a, b);
}

// ---------------------------------------------------------------------------
// bf16 GEMM (R13 measured-best): BM=BN=128, BK=64, 256 thr / 8 warps (4x2),
// warp tile 32x64. A,B tiles: 128 rows x (32+4) words, double-buffered (72KB).
// ---------------------------------------------------------------------------
#define TG_SMEM (18432 * 4)   // 72 KB

template <bool RES, bool OBF16, bool QSC>
__global__ __launch_bounds__(256, 2) void tgemm(
    const uint32_t* __restrict__ A, const uint32_t* __restrict__ Bt,
    const float* __restrict__ bias, const float* __restrict__ resid,
    void* __restrict__ Cp, int M, int N)
{
    extern __shared__ __align__(16) uint32_t sm[];
    uint32_t* Abuf[2] = {sm, sm + 4608};
    uint32_t* Bbuf[2] = {sm + 9216, sm + 13824};

    const int tid  = threadIdx.x;
    const int warp = tid >> 5, lane = tid & 31;
    const int gid  = lane >> 2, tig = lane & 3;
    const int wr   = warp >> 1, wc = warp & 1;
    const int bx = blockIdx.x, by = blockIdx.y;

    const uint32_t* Ag = A  + (size_t)(by * 128) * KW;
    const uint32_t* Bg = Bt + (size_t)(bx * 128) * KW;

    float acc[2][8][4];
#pragma unroll
    for (int mt = 0; mt < 2; mt++)
#pragma unroll
        for (int nt = 0; nt < 8; nt++)
#pragma unroll
            for (int r = 0; r < 4; r++) acc[mt][nt][r] = 0.f;

    uint4 ra[4], rb[4];
    auto ldg = [&](int c) {
        int w0 = c * 32;
#pragma unroll
        for (int i = 0; i < 4; i++) {
            int j = tid + i * 256;
            int r = j >> 3, seg = j & 7;
            ra[i] = *(const uint4*)(Ag + (size_t)r * KW + w0 + seg * 4);
            rb[i] = *(const uint4*)(Bg + (size_t)r * KW + w0 + seg * 4);
        }
    };
    auto sts = [&](int s) {
#pragma unroll
        for (int i = 0; i < 4; i++) {
            int j = tid + i * 256;
            int r = j >> 3, seg = j & 7;
            *(uint4*)&Abuf[s][r * 36 + seg * 4] = ra[i];
            *(uint4*)&Bbuf[s][r * 36 + seg * 4] = rb[i];
        }
    };

    ldg(0); sts(0);
    __syncthreads();

    const int tiles = 8;                     // K = 512 = 8 x 64
    for (int t = 0; t < tiles; t++) {
        const int s = t & 1;
        if (t + 1 < tiles) ldg(t + 1);

        const uint32_t* As = Abuf[s];
        const uint32_t* Bs = Bbuf[s];

#pragma unroll
        for (int kkk = 0; kkk < 4; kkk++) {
            uint32_t af[2][4];
#pragma unroll
            for (int mt = 0; mt < 2; mt++) {
                int mb = wr * 32 + mt * 16;
                ldmx4(af[mt][0], af[mt][1], af[mt][2], af[mt][3],
                      &As[(mb + (lane & 15)) * 36 + kkk * 8 + (lane >> 4) * 4]);
            }
#pragma unroll
            for (int nt2 = 0; nt2 < 4; nt2++) {
                uint32_t r0, r1, r2, r3;
                int rr = wc * 64 + nt2 * 16 + (lane & 7) + ((lane >> 4) << 3);
                int ww = kkk * 8 + ((lane & 8) >> 1);
                ldmx4(r0, r1, r2, r3, &Bs[rr * 36 + ww]);
                uint32_t b0[2] = {r0, r1};
                uint32_t b1[2] = {r2, r3};
#pragma unroll
                for (int mt = 0; mt < 2; mt++) {
                    mma_bf16(acc[mt][2 * nt2 + 0], af[mt], b0);
                    mma_bf16(acc[mt][2 * nt2 + 1], af[mt], b1);
                }
            }
        }

        if (t + 1 < tiles) sts(s ^ 1);
        __syncthreads();
    }

#pragma unroll
    for (int mt = 0; mt < 2; mt++) {
#pragma unroll
        for (int r2 = 0; r2 < 2; r2++) {
            int row = by * 128 + wr * 32 + mt * 16 + gid + r2 * 8;
#pragma unroll
            for (int nt = 0; nt < 8; nt++) {
                int col = bx * 128 + wc * 64 + nt * 8 + tig * 2;
                float2 bz = *(const float2*)(bias + col);
                float ox = acc[mt][nt][r2 * 2 + 0] + bz.x;
                float oy = acc[mt][nt][r2 * 2 + 1] + bz.y;
                if (RES) {
                    float2 rr = *(const float2*)(resid + (size_t)row * N + col);
                    ox += rr.x; oy += rr.y;
                }
                if (QSC && ((col % 192) < 64)) { ox *= SCALE_L2E; oy *= SCALE_L2E; }
                if (OBF16) {
                    ((uint32_t*)Cp)[(size_t)row * (N / 2) + col / 2] = packbf(ox, oy);
                } else {
                    float2 o; o.x = ox; o.y = oy;
                    *(float2*)((float*)Cp + (size_t)row * N + col) = o;
                }
            }
        }
    }
}

// ---------------------------------------------------------------------------
// Flash attention (R14 measured-best, 98.3us): CTA = 128 queries x (b,h),
// 8 warps x 16 rows, fixed-max ex2 softmax, P in registers,
// double-buffered K/V, SINGLE sync per tile.
// ---------------------------------------------------------------------------
__global__ __launch_bounds__(256, 2) void fattn(
    const uint32_t* __restrict__ qkv, uint32_t* __restrict__ out)
{
    __shared__ uint32_t KV[2][2][64 * 36];   // 36 KB

    const int tid  = threadIdx.x;
    const int warp = tid >> 5, lane = tid & 31;
    const int gid  = lane >> 2, tig = lane & 3;
    const int wrow = warp * 16;
    const int qt = blockIdx.x, h = blockIdx.y, b = blockIdx.z;

    const uint32_t* base = qkv + ((size_t)b * NTOK) * (QKV_N / 2) + h * 96;

    // ---- stage Q into KV region, extract frags ----
    {
        uint32_t* qs = &KV[0][0][0];
#pragma unroll
        for (int i = 0; i < 4; i++) {
            int j = tid + i * 256;
            int r = j >> 3, seg = j & 7;
            *(uint4*)&qs[r * 36 + seg * 4] =
                *(const uint4*)(base + (size_t)(qt * 128 + r) * (QKV_N / 2) + seg * 4);
        }
    }
    __syncthreads();

    uint32_t qf[4][4];
    {
        const uint32_t* qs = &KV[0][0][0];
#pragma unroll
        for (int kki = 0; kki < 4; kki++)
            ldmx4(qf[kki][0], qf[kki][1], qf[kki][2], qf[kki][3],
                  &qs[(wrow + (lane & 15)) * 36 + kki * 8 + (lane >> 4) * 4]);
    }
    __syncthreads();

    uint4 pre[4];
    auto ldg_kv = [&](int kt) {
        const uint32_t* kb = base + (size_t)(kt * 64) * (QKV_N / 2);
#pragma unroll
        for (int i = 0; i < 4; i++) {
            int j = tid + i * 256;
            int kv = j >> 9, jj = j & 511;
            int r = jj >> 3, seg = jj & 7;
            pre[i] = *(const uint4*)(kb + (size_t)r * (QKV_N / 2) + 32 + kv * 32
                                        + seg * 4);
        }
    };
    auto sts_kv = [&](int s) {
#pragma unroll
        for (int i = 0; i < 4; i++) {
            int j = tid + i * 256;
            int kv = j >> 9, jj = j & 511;
            int r = jj >> 3, seg = jj & 7;
            *(uint4*)&KV[s][kv][r * 36 + seg * 4] = pre[i];
        }
    };

    float o[8][4];
#pragma unroll
    for (int nt = 0; nt < 8; nt++)
#pragma unroll
        for (int r = 0; r < 4; r++) o[nt][r] = 0.f;
    float l0 = 0.f, l1 = 0.f;

    ldg_kv(0);
    sts_kv(0);
    __syncthreads();

    for (int kt = 0; kt < 16; kt++) {
        const int s = kt & 1;
        if (kt + 1 < 16) ldg_kv(kt + 1);

        const uint32_t* ks = &KV[s][0][0];
        const uint32_t* vs = &KV[s][1][0];

        // ---- S = Q @ K^T ----
        float sc[8][4];
#pragma unroll
        for (int nt = 0; nt < 8; nt++)
#pragma unroll
            for (int r = 0; r < 4; r++) sc[nt][r] = 0.f;
#pragma unroll
        for (int kki = 0; kki < 4; kki++) {
#pragma unroll
            for (int nt2 = 0; nt2 < 4; nt2++) {
                uint32_t r0, r1, r2, r3;
                int rr = nt2 * 16 + (lane & 7) + ((lane >> 4) << 3);
                int ww = kki * 8 + ((lane & 8) >> 1);
                ldmx4(r0, r1, r2, r3, &ks[rr * 36 + ww]);
                uint32_t b0[2] = {r0, r1};
                uint32_t b1[2] = {r2, r3};
                mma_bf16(sc[2 * nt2 + 0], qf[kki], b0);
                mma_bf16(sc[2 * nt2 + 1], qf[kki], b1);
            }
        }

        // ---- fixed-max softmax: p = ex2(s) ----
        uint32_t pa[4][4];
#pragma unroll
        for (int nt = 0; nt < 8; nt++) {
            float p0 = ex2(sc[nt][0]);
            float p1 = ex2(sc[nt][1]);
            float p2 = ex2(sc[nt][2]);
            float p3 = ex2(sc[nt][3]);
            l0 += p0 + p1;
            l1 += p2 + p3;
            sc[nt][0] = p0; sc[nt][1] = p1; sc[nt][2] = p2; sc[nt][3] = p3;
        }
#pragma unroll
        for (int kkk = 0; kkk < 4; kkk++) {
            pa[kkk][0] = packbf(sc[2 * kkk    ][0], sc[2 * kkk    ][1]);
            pa[kkk][1] = packbf(sc[2 * kkk    ][2], sc[2 * kkk    ][3]);
            pa[kkk][2] = packbf(sc[2 * kkk + 1][0], sc[2 * kkk + 1][1]);
            pa[kkk][3] = packbf(sc[2 * kkk + 1][2], sc[2 * kkk + 1][3]);
        }

        // ---- O += P @ V ----
#pragma unroll
        for (int kkk = 0; kkk < 4; kkk++) {
#pragma unroll
            for (int ntp = 0; ntp < 4; ntp++) {
                uint32_t r0, r1, r2, r3;
                ldmx4t(r0, r1, r2, r3,
                       &vs[(kkk * 16 + (lane & 15)) * 36 + ntp * 8 + (lane >> 4) * 4]);
                uint32_t vb0[2] = {r0, r1};
                uint32_t vb1[2] = {r2, r3};
                mma_bf16(o[2 * ntp + 0], pa[kkk], vb0);
                mma_bf16(o[2 * ntp + 1], pa[kkk], vb1);
            }
        }

        // single barrier per tile: buffer s^1 was drained by end-of-(kt-1) sync
        if (kt + 1 < 16) sts_kv(s ^ 1);
        __syncthreads();
    }

    // ---- epilogue ----
    l0 += __shfl_xor_sync(0xffffffffu, l0, 1);
    l0 += __shfl_xor_sync(0xffffffffu, l0, 2);
    l1 += __shfl_xor_sync(0xffffffffu, l1, 1);
    l1 += __shfl_xor_sync(0xffffffffu, l1, 2);
    float i0 = 1.f / l0, i1 = 1.f / l1;

    int row = b * NTOK + qt * 128 + wrow + gid;
    uint32_t* op0 = out + (size_t)row * (ATT_N / 2) + h * 32;
    uint32_t* op1 = out + (size_t)(row + 8) * (ATT_N / 2) + h * 32;
#pragma unroll
    for (int nt = 0; nt < 8; nt++) {
        op0[nt * 4 + tig] = packbf(o[nt][0] * i0, o[nt][1] * i0);
        op1[nt * 4 + tig] = packbf(o[nt][2] * i1, o[nt][3] * i1);
    }
}

// ---------------------------------------------------------------------------
extern "C" void kernel_launch(void* const* d_in, const int* in_sizes, int n_in,
                              void* d_out, int out_size)
{
    const float* ft    = (const float*)d_in[0];
    const float* w_qkv = (const float*)d_in[1];
    const float* b_qkv = (const float*)d_in[2];
    const float* w_out = (const float*)d_in[3];
    const float* b_out = (const float*)d_in[4];
    float* out = (float*)d_out;

    uint32_t *xbf, *qkv, *att, *wqkvT, *woutT;
    cudaGetSymbolAddress((void**)&xbf,   g_xbf);
    cudaGetSymbolAddress((void**)&qkv,   g_qkv);
    cudaGetSymbolAddress((void**)&att,   g_att);
    cudaGetSymbolAddress((void**)&wqkvT, g_wqkvT);
    cudaGetSymbolAddress((void**)&woutT, g_woutT);

    cudaFuncSetAttribute(tgemm<false, true, true>,
                         cudaFuncAttributeMaxDynamicSharedMemorySize, TG_SMEM);
    cudaFuncSetAttribute(tgemm<true, false, false>,
                         cudaFuncAttributeMaxDynamicSharedMemorySize, TG_SMEM);

    cvt_x<<<(M_TOT * KW + 255) / 256, 256>>>(ft, xbf, M_TOT * KW);
    { dim3 g(QKV_N / 256, KW); pack_wt<<<g, 256>>>(w_qkv, wqkvT, QKV_N); }
    { dim3 g(ATT_N / 256, KW); pack_wt<<<g, 256>>>(w_out, woutT, ATT_N); }

    // 1) QKV projection: bf16 out, Q cols pre-scaled by SCALE*log2e
    {
        dim3 grid(QKV_N / 128, M_TOT / 128);
        tgemm<false, true, true><<<grid, 256, TG_SMEM>>>(
            xbf, wqkvT, b_qkv, nullptr, qkv, M_TOT, QKV_N);
    }
    // 2) attention
    {
        dim3 grid(NTOK / 128, NH, BB);
        fattn<<<grid, 256>>>(qkv, att);
    }
    // 3) output projection: fp32 out + bias + residual
    {
        dim3 grid(ATT_N / 128, M_TOT / 128);
        tgemm<true, false, false><<<grid, 256, TG_SMEM>>>(
            att, woutT, b_out, ft, out, M_TOT, ATT_N);
    }
}